// round 13
// baseline (speedup 1.0000x reference)
#include <cuda_runtime.h>

#define NTIME 1024
#define NB    65536
#define TPB   128   // 4 warps/block; 8 batches per warp (4 lanes per batch)

__global__ void __launch_bounds__(TPB)
bts_interp_kernel(const float* __restrict__ times,
                  const float* __restrict__ values,
                  const float* __restrict__ tq,
                  float* __restrict__ out)
{
    const unsigned FULL = 0xFFFFFFFFu;
    const int lane = threadIdx.x & 31;
    const int warp = threadIdx.x >> 5;
    const int sub  = lane >> 3;                       // 0..3: quarter of the coarse scan
    const int b    = blockIdx.x * 32 + warp * 8 + (lane & 7);

    const float t = __ldg(&tq[b]);
    const float* col = times + b;

    // ── Coarse (split 4 ways, coalesced): 64 rows 15, 31, ..., 1023.
    // Sub s scans coarse indices s*16 .. s*16+15 (a sorted segment).
    int   m  = 0;          // successes within my segment
    float lo = 0.0f;       // last success value in my segment
    float hi = 0.0f;       // first failure value in my segment
#pragma unroll
    for (int chunk = 0; chunk < 2; ++chunk) {
        float x[8];
#pragma unroll
        for (int i = 0; i < 8; ++i) {
            const int j = sub * 16 + chunk * 8 + i;           // coarse index 0..63
            x[i] = __ldg(col + (size_t)(16 * j + 15) * NB);
        }
#pragma unroll
        for (int i = 0; i < 8; ++i) {
            const int jl = chunk * 8 + i;                     // local 0..15
            if (x[i] <= t) { lo = x[i]; m++; }
            else if (jl == m) hi = x[i];                      // first local failure
        }
    }

    // ── Merge the 4 sorted segments: levels w = 8 (len 16) and w = 16 (len 32).
#pragma unroll
    for (int lvl = 0; lvl < 2; ++lvl) {
        const int w   = 8 << lvl;
        const int len = 16 << lvl;
        const int   mo  = __shfl_xor_sync(FULL, m,  w);
        const float loo = __shfl_xor_sync(FULL, lo, w);
        const float hio = __shfl_xor_sync(FULL, hi, w);
        const bool lower = ((lane & w) == 0);                 // am I the lower segment?
        const int   mA  = lower ? m   : mo;
        const int   mB  = lower ? mo  : m;
        const float loA = lower ? lo  : loo;
        const float loB = lower ? loo : lo;
        const float hiA = lower ? hi  : hio;
        const float hiB = lower ? hio : hi;
        m  = mA + mB;
        lo = (mB > 0)   ? loB : loA;                          // last success overall
        hi = (mA < len) ? hiA : hiB;                          // first failure overall
    }
    // Now every lane: m = #coarse <= t (0..64), lo = times[16m-1], hi = times[16m+15].

    int c = m << 4;                     // count in [c, c+15]
    const bool hiwrap = (m == 64);      // count == 1024

    // ── Fine: 4 binary rounds (byte-minimal), redundant across the 4 sub-lanes
    // (same address -> L1 dedup). Bracket invariant: at exit lo == times[c-1],
    // hi == times[c] bit-exact.
#pragma unroll
    for (int step = 8; step >= 1; step >>= 1) {
        int r = c + step - 1;
        if (hiwrap) r = NTIME - 1;                            // in-bounds; discarded
        const float x = __ldg(col + (size_t)r * NB);
        if (x <= t) { lo = x; c += step; }
        else        { hi = x; }
    }

    // ── Values: rows c-1 and c, clamped (hiwrap lanes carry garbage c ~ 1039).
    int ia = c - 1;
    if (ia < 0)         ia = 0;
    if (ia > NTIME - 1) ia = NTIME - 1;
    int ib = c;
    if (ib > NTIME - 1) ib = NTIME - 1;

    const float va = __ldg(&values[(size_t)ia * NB + b]);
    const float vb = __ldg(&values[(size_t)ib * NB + b]);

    if (sub == 0) {
        const bool wrap = hiwrap || (c == 0);                 // count == 1024 or 0
        float result;
        if (!wrap) {
            const float s0 = (vb - va) / (hi - lo);           // exact bracket knots
            result = va + s0 * (t - lo);
        } else {
            // Reference wrap: iv = 1023, isl = 1022.
            const float tp = __ldg(&times [(size_t)(NTIME - 2) * NB + b]);
            const float tl = __ldg(&times [(size_t)(NTIME - 1) * NB + b]);
            const float vp = __ldg(&values[(size_t)(NTIME - 2) * NB + b]);
            const float vl = __ldg(&values[(size_t)(NTIME - 1) * NB + b]);
            const float s0 = (vl - vp) / (tl - tp);
            result = vl + s0 * (t - tl);
        }
        out[b] = result;
    }
}

extern "C" void kernel_launch(void* const* d_in, const int* in_sizes, int n_in,
                              void* d_out, int out_size)
{
    const float* times  = (const float*)d_in[0];
    const float* values = (const float*)d_in[1];
    const float* tq     = (const float*)d_in[2];
    float* out = (float*)d_out;

    // 4 threads per batch: 262144 threads, 2048 blocks of 128.
    bts_interp_kernel<<<(NB * 4) / TPB, TPB>>>(times, values, tq, out);
}

// round 14
// speedup vs baseline: 1.2567x; 1.2567x over previous
#include <cuda_runtime.h>

#define NTIME 1024
#define NB    65536
#define TPB   128   // 4 warps/block; 16 batches per warp (2 lanes per batch)

__global__ void __launch_bounds__(TPB)
bts_interp_kernel(const float* __restrict__ times,
                  const float* __restrict__ values,
                  const float* __restrict__ tq,
                  float* __restrict__ out)
{
    const unsigned FULL = 0xFFFFFFFFu;
    const int lane = threadIdx.x & 31;
    const int warp = threadIdx.x >> 5;
    const int half = lane >> 4;                       // 0 = lower pair half
    const int b    = blockIdx.x * 64 + warp * 16 + (lane & 15);

    const float t = __ldg(&tq[b]);
    const float* col = times + b;

    // ── Coarse (split 2-way, coalesced): 64 rows 15,31,...,1023.
    // Half h scans coarse indices h*32 .. h*32+31 (a sorted segment).
    int   m_h  = 0;
    float lo_h = 0.0f, hi_h = 0.0f;
#pragma unroll
    for (int chunk = 0; chunk < 4; ++chunk) {
        float x[8];
#pragma unroll
        for (int i = 0; i < 8; ++i) {
            const int j = half * 32 + chunk * 8 + i;          // coarse index 0..63
            x[i] = __ldg(col + (size_t)(16 * j + 15) * NB);
        }
#pragma unroll
        for (int i = 0; i < 8; ++i) {
            const int jl = chunk * 8 + i;                     // local 0..31
            if (x[i] <= t) { lo_h = x[i]; m_h++; }
            else if (jl == m_h) hi_h = x[i];                  // first local failure
        }
    }

    // Merge halves (sorted column: upper-segment success implies lower segment full).
    const int   m_o  = __shfl_xor_sync(FULL, m_h,  16);
    const float lo_o = __shfl_xor_sync(FULL, lo_h, 16);
    const float hi_o = __shfl_xor_sync(FULL, hi_h, 16);
    const int   m0 = half ? m_o  : m_h;
    const int   m1 = half ? m_h  : m_o;
    const float lo0 = half ? lo_o : lo_h;
    const float lo1 = half ? lo_h : lo_o;
    const float hi0 = half ? hi_o : hi_h;
    const float hi1 = half ? hi_h : hi_o;

    const int m = m0 + m1;                  // identical in both halves
    float lo = (m1 > 0)  ? lo1 : lo0;       // = times[16m-1]  (valid iff m > 0)
    float hi = (m0 < 32) ? hi0 : hi1;       // = times[16m+15] (valid iff m < 64)

    int c = m << 4;                         // count in [c, c+15]
    const bool hiwrap = (m == 64);          // count == 1024

    // ── Fine: 4 binary probes (wavefront-minimal), executed REDUNDANTLY by
    // both pair-halves (identical c in both halves -> same addresses -> the
    // warp-LDG dedups to 16 lines; zero extra wavefronts, no shuffles).
    // Bracket invariant: at exit lo == times[c-1], hi == times[c] bit-exact.
#pragma unroll
    for (int step = 8; step >= 1; step >>= 1) {
        int r = c + step - 1;
        if (hiwrap) r = NTIME - 1;          // in-bounds; result discarded
        const float x = __ldg(col + (size_t)r * NB);
        if (x <= t) { lo = x; c += step; }
        else        { hi = x; }
    }

    // ── Values (split 1/1): rows c-1 / c, clamped (hiwrap lanes have c ~ 1040).
    int ia = c - 1;
    if (ia < 0)         ia = 0;
    if (ia > NTIME - 1) ia = NTIME - 1;
    int ib = c;
    if (ib > NTIME - 1) ib = NTIME - 1;

    float v_mine;
    if (half == 0) v_mine = __ldg(&values[(size_t)ia * NB + b]);
    else           v_mine = __ldg(&values[(size_t)ib * NB + b]);
    const float v_oth = __shfl_xor_sync(FULL, v_mine, 16);

    if (half == 0) {
        const bool wrap = hiwrap || (c == 0);       // count == 1024 or 0
        float result;
        if (!wrap) {
            const float va = v_mine;                // values[c-1]
            const float vb = v_oth;                 // values[c]
            const float s0 = (vb - va) / (hi - lo); // bit-exact bracket knots
            result = va + s0 * (t - lo);
        } else {
            // Reference wrap: iv = 1023, isl = 1022.
            const float tp = __ldg(&times [(size_t)(NTIME - 2) * NB + b]);
            const float tl = __ldg(&times [(size_t)(NTIME - 1) * NB + b]);
            const float vp = __ldg(&values[(size_t)(NTIME - 2) * NB + b]);
            const float vl = __ldg(&values[(size_t)(NTIME - 1) * NB + b]);
            const float s0 = (vl - vp) / (tl - tp);
            result = vl + s0 * (t - tl);
        }
        out[b] = result;
    }
}

extern "C" void kernel_launch(void* const* d_in, const int* in_sizes, int n_in,
                              void* d_out, int out_size)
{
    const float* times  = (const float*)d_in[0];
    const float* values = (const float*)d_in[1];
    const float* tq     = (const float*)d_in[2];
    float* out = (float*)d_out;

    // 2 threads per batch: 131072 threads, 1024 blocks of 128.
    bts_interp_kernel<<<(NB * 2) / TPB, TPB>>>(times, values, tq, out);
}